// round 7
// baseline (speedup 1.0000x reference)
#include <cuda_runtime.h>
#include <math.h>

#define BB 64
#define FF 512
#define EE 256
#define HH 8
#define DD 32
#define LL 4

// Per-head collapsed scalars, written by kernel A, read by kernel B.
// Layout: g_scal[h] = {A0, P, R, VA, VB} (already 1/sqrt(D)-scaled where needed)
__device__ __align__(128) float g_scal[HH][8];

__device__ __forceinline__ float ex2f(float x) {
    float y;
    asm("ex2.approx.ftz.f32 %0, %1;" : "=f"(y) : "f"(x));
    return y;
}

// ---------------------------------------------------------------------------
// Kernel A: grid = 8 (one block per head h = column group), 256 threads.
// Warp w computes matrix m = w&3 over row-half = w>>2 for this head's 32
// columns. Then warps 0..3 finalize each matrix; warp 0 forms the five
// 32-length dot products and writes 5 floats.
//   kw = (emb_w @ k_w)[cols]      vw = (emb_w @ v_w)[cols]
//   vb = (emb_b @ v_w + v_b)[cols] qv = (emb_b @ q_w + q_b)[cols]
//   A0 = scale*qv.kw  P = scale*vw.kw  R = scale*vb.kw  VA = vw.aw  VB = vb.aw
// ---------------------------------------------------------------------------
__global__ void __launch_bounds__(256)
precompute_kernel(const float* __restrict__ emb_w,
                  const float* __restrict__ emb_b,
                  const float* __restrict__ q_w,
                  const float* __restrict__ q_b,
                  const float* __restrict__ k_w,
                  const float* __restrict__ v_w,
                  const float* __restrict__ v_b,
                  const float* __restrict__ attn_w) {
    __shared__ float s_pre[4][2][32];   // [matrix][row-half][lane]
    __shared__ float s_fin[4][32];      // finalized vectors

    const int h    = blockIdx.x;        // head == column group
    const int t    = threadIdx.x;
    const int warp = t >> 5;
    const int lane = t & 31;
    const int m    = warp & 3;          // 0:kw 1:vw 2:vb 3:qv
    const int half = warp >> 2;
    const int col  = h * 32 + lane;

    const float* vecsrc = (m <= 1) ? emb_w : emb_b;
    const float* mat    = (m == 0) ? k_w : (m == 3 ? q_w : v_w);
    const float* mp     = mat + (half * 128) * EE + col;

    // this warp's 128 embedding entries (4 per lane)
    float ev0 = vecsrc[half * 128 +  0 + lane];
    float ev1 = vecsrc[half * 128 + 32 + lane];
    float ev2 = vecsrc[half * 128 + 64 + lane];
    float ev3 = vecsrc[half * 128 + 96 + lane];
    float bias = 0.f;
    if (half == 0) {
        if (m == 2) bias = v_b[col];
        if (m == 3) bias = q_b[col];
    }
    // prefetch aw early (only warp 0 uses it later)
    float aw = (warp == 0) ? attn_w[col] : 0.f;

    float a0 = 0.f, a1 = 0.f, a2 = 0.f, a3 = 0.f;
    #pragma unroll
    for (int e = 0; e < 32; e++) {
        a0 = fmaf(__shfl_sync(0xffffffffu, ev0, e), mp[(e      ) * EE], a0);
        a1 = fmaf(__shfl_sync(0xffffffffu, ev1, e), mp[(e +  32) * EE], a1);
        a2 = fmaf(__shfl_sync(0xffffffffu, ev2, e), mp[(e +  64) * EE], a2);
        a3 = fmaf(__shfl_sync(0xffffffffu, ev3, e), mp[(e +  96) * EE], a3);
    }
    s_pre[m][half][lane] = (a0 + a1) + (a2 + a3);
    __syncthreads();

    if (half == 0) {
        s_fin[m][lane] = s_pre[m][0][lane] + s_pre[m][1][lane] + bias;
    }
    __syncthreads();

    if (warp == 0) {
        float kw = s_fin[0][lane];
        float vw = s_fin[1][lane];
        float vb = s_fin[2][lane];
        float qv = s_fin[3][lane];

        const float scale = 0.17677669529663687f;   // 1/sqrt(32)
        float A0 = qv * kw, P = vw * kw, R = vb * kw, VA = vw * aw, VB = vb * aw;
        #pragma unroll
        for (int o = 16; o > 0; o >>= 1) {
            A0 += __shfl_xor_sync(0xffffffffu, A0, o);
            P  += __shfl_xor_sync(0xffffffffu, P,  o);
            R  += __shfl_xor_sync(0xffffffffu, R,  o);
            VA += __shfl_xor_sync(0xffffffffu, VA, o);
            VB += __shfl_xor_sync(0xffffffffu, VB, o);
        }
        if (lane == 0) {
            g_scal[h][0] = A0 * scale;
            g_scal[h][1] = P  * scale;
            g_scal[h][2] = R  * scale;
            g_scal[h][3] = VA;
            g_scal[h][4] = VB;
        }
    }
}

// ---------------------------------------------------------------------------
// Kernel B: grid = 64 (one block per batch), 256 threads = 8 warps = 8 heads.
// Warp h: load full x_b[512] into registers (coalesced), 3-stat butterfly,
// then the L=4 scalar softmax recursion using the 5 precomputed head scalars
// (uniform-address loads, issued concurrently with the feature loads).
// ---------------------------------------------------------------------------
__global__ void __launch_bounds__(256, 8)
attn_kernel(const float* __restrict__ features,
            const float* __restrict__ attn_b,
            float* __restrict__ out) {
    __shared__ float s_ox[HH], s_hc[HH];

    const int b    = blockIdx.x;
    const int t    = threadIdx.x;
    const int warp = t >> 5;
    const int lane = t & 31;

    // ---- all loads issued up front ----
    const float* xb = features + b * FF;
    float xr[FF / 32];
    #pragma unroll
    for (int i = 0; i < FF / 32; i++) xr[i] = xb[lane + i * 32];

    float A0 = g_scal[warp][0];
    float P  = g_scal[warp][1];
    float R  = g_scal[warp][2];
    float VA = g_scal[warp][3];
    float VB = g_scal[warp][4];
    float ab = attn_b[0];

    // ---- warp-local stats ----
    float S = 0.f, xmax = -1e30f, xmin = 1e30f;
    #pragma unroll
    for (int i = 0; i < FF / 32; i++) {
        S += xr[i];
        xmax = fmaxf(xmax, xr[i]);
        xmin = fminf(xmin, xr[i]);
    }
    #pragma unroll
    for (int o = 16; o > 0; o >>= 1) {
        S   += __shfl_xor_sync(0xffffffffu, S,   o);
        xmax = fmaxf(xmax, __shfl_xor_sync(0xffffffffu, xmax, o));
        xmin = fminf(xmin, __shfl_xor_sync(0xffffffffu, xmin, o));
    }

    // ---- L-step scalar softmax recursion (warp-local, tree sums) ----
    const float L2E = 1.4426950408889634f;
    float alpha = A0;
    float m = 0.f;
    #pragma unroll
    for (int it = 0; it < LL; it++) {
        float a2 = alpha * L2E;
        float M2 = (alpha >= 0.f) ? a2 * xmax : a2 * xmin;   // exact max logit
        float w[FF / 32];
        #pragma unroll
        for (int i = 0; i < FF / 32; i++) w[i] = ex2f(fmaf(a2, xr[i], -M2));
        float sw0 = w[0] + w[1],   sw1 = w[2] + w[3];
        float sw2 = w[4] + w[5],   sw3 = w[6] + w[7];
        float sw4 = w[8] + w[9],   sw5 = w[10] + w[11];
        float sw6 = w[12] + w[13], sw7 = w[14] + w[15];
        float sw = ((sw0 + sw1) + (sw2 + sw3)) + ((sw4 + sw5) + (sw6 + sw7));
        float t0 = fmaf(xr[1],  w[1],  xr[0]  * w[0]);
        float t1 = fmaf(xr[3],  w[3],  xr[2]  * w[2]);
        float t2 = fmaf(xr[5],  w[5],  xr[4]  * w[4]);
        float t3 = fmaf(xr[7],  w[7],  xr[6]  * w[6]);
        float t4 = fmaf(xr[9],  w[9],  xr[8]  * w[8]);
        float t5 = fmaf(xr[11], w[11], xr[10] * w[10]);
        float t6 = fmaf(xr[13], w[13], xr[12] * w[12]);
        float t7 = fmaf(xr[15], w[15], xr[14] * w[14]);
        float sxw = ((t0 + t1) + (t2 + t3)) + ((t4 + t5) + (t6 + t7));
        #pragma unroll
        for (int o = 16; o > 0; o >>= 1) {
            sw  += __shfl_xor_sync(0xffffffffu, sw,  o);
            sxw += __shfl_xor_sync(0xffffffffu, sxw, o);
        }
        m = __fdividef(sxw, sw);
        alpha = fmaf(m, P, R);
    }

    if (lane == 0) {
        s_ox[warp] = fmaf(m, VA, VB);                          // Qc contribution
        s_hc[warp] = fmaf(S - m, VA, (float)(FF - 1) * VB);    // (v_sum - Qc)
    }
    __syncthreads();   // single block sync

    float ox = ab, cc = ab;
    #pragma unroll
    for (int hh = 0; hh < HH; hh++) { ox += s_ox[hh]; cc += s_hc[hh]; }

    out[b * FF + t]                 = ox;
    out[b * FF + t + 256]           = ox;
    out[BB * FF + b * FF + t]       = cc;
    out[BB * FF + b * FF + t + 256] = cc;
}

extern "C" void kernel_launch(void* const* d_in, const int* in_sizes, int n_in,
                              void* d_out, int out_size) {
    const float* features = (const float*)d_in[0];
    const float* emb_w    = (const float*)d_in[1];
    const float* emb_b    = (const float*)d_in[2];
    const float* q_w      = (const float*)d_in[3];
    const float* q_b      = (const float*)d_in[4];
    const float* k_w      = (const float*)d_in[5];
    // d_in[6] = k_b: cancels in softmax, unused
    const float* v_w      = (const float*)d_in[7];
    const float* v_b      = (const float*)d_in[8];
    const float* attn_w   = (const float*)d_in[9];
    const float* attn_b   = (const float*)d_in[10];
    float* out = (float*)d_out;

    precompute_kernel<<<8, 256>>>(emb_w, emb_b, q_w, q_b, k_w, v_w, v_b, attn_w);
    attn_kernel<<<BB, 256>>>(features, attn_b, out);
}